// round 1
// baseline (speedup 1.0000x reference)
#include <cuda_runtime.h>

#define NODES 7
#define CH 256
#define HID 128
#define P_TOTAL 65536           // 16*64*64
#define P64 (P_TOTAL / 2)       // u64 (2-point) granularity

__device__ float g_nw[2 * NODES * CH];   // new_weight [b, n, c]
__device__ float g_n2[2 * NODES];        // n2 [b, n]

// ---------------------------------------------------------------------------
// Tiny precompute: new_weight = inp @ weight  [2,7,256], n2 = inp @ nfh [2,7]
// ---------------------------------------------------------------------------
__global__ void precompute_kernel(const float* __restrict__ inp,
                                  const float* __restrict__ nfh,
                                  const float* __restrict__ weight) {
    int bn = blockIdx.x;            // 0..13 = b*7+n
    int c  = threadIdx.x;           // 0..255
    __shared__ float sh_inp[HID];
    __shared__ float red[HID];
    if (c < HID) sh_inp[c] = inp[bn * HID + c];
    __syncthreads();
    float acc = 0.f;
#pragma unroll 8
    for (int h = 0; h < HID; ++h)
        acc += sh_inp[h] * weight[h * CH + c];
    g_nw[bn * CH + c] = acc;
    if (c < HID) red[c] = sh_inp[c] * nfh[c];
    __syncthreads();
    if (c == 0) {
        float s = 0.f;
        for (int h = 0; h < HID; ++h) s += red[h];
        g_n2[bn] = s;
    }
}

// ---------------------------------------------------------------------------
// Packed f32x2 helpers (Blackwell fma.rn.f32x2 — 2x FFMA throughput per issue)
// ---------------------------------------------------------------------------
__device__ __forceinline__ unsigned long long fma2(unsigned long long a,
                                                   unsigned long long b,
                                                   unsigned long long c) {
    unsigned long long d;
    asm("fma.rn.f32x2 %0, %1, %2, %3;" : "=l"(d) : "l"(a), "l"(b), "l"(c));
    return d;
}
__device__ __forceinline__ unsigned long long pack2(float x, float y) {
    unsigned long long r;
    asm("mov.b64 %0, {%1, %2};" : "=l"(r) : "f"(x), "f"(y));
    return r;
}
__device__ __forceinline__ void unpack2(unsigned long long v, float& x, float& y) {
    asm("mov.b64 {%0, %1}, %2;" : "=f"(x), "=f"(y) : "l"(v));
}

// ---------------------------------------------------------------------------
// Fused main kernel: n1 -> softmax -> attn @ new_weight -> relu
// Each thread handles 2 consecutive spatial points (one u64 lane).
// Grid: 512 blocks (256 per batch), 128 threads.
// ---------------------------------------------------------------------------
__global__ void __launch_bounds__(128) main_kernel(
    const float* __restrict__ res,     // [2, 256, 65536]
    const float* __restrict__ Wres,    // [256, 7]
    float* __restrict__ out)           // [2, 256, 65536]
{
    __shared__ unsigned long long Wd[CH][8];   // duplicated node_fea_for_res
    __shared__ unsigned long long NWd[CH][8];  // duplicated new_weight (this batch)

    const int tid  = threadIdx.x;
    const int b    = blockIdx.x >> 8;   // 0..1
    const int tile = blockIdx.x & 255;  // 0..255

    // Stage duplicated weights into shared
    for (int c = tid; c < CH; c += 128) {
#pragma unroll
        for (int n = 0; n < NODES; ++n) {
            float w  = Wres[c * NODES + n];
            Wd[c][n] = pack2(w, w);
            float nw = g_nw[(b * NODES + n) * CH + c];
            NWd[c][n] = pack2(nw, nw);
        }
        Wd[c][7]  = 0ull;
        NWd[c][7] = 0ull;
    }
    float n2s[NODES];
#pragma unroll
    for (int n = 0; n < NODES; ++n) n2s[n] = g_n2[b * NODES + n];
    __syncthreads();

    const unsigned long long gidx = (unsigned long long)tile * 128 + tid;
    const unsigned long long* rf =
        (const unsigned long long*)res + (unsigned long long)b * CH * P64 + gidx;

    unsigned long long acc[NODES];
#pragma unroll
    for (int n = 0; n < NODES; ++n) acc[n] = 0ull;

    // ---- Pass 1: n1[p, n] = sum_c rf[c, p] * Wres[c, n], packed over 2 points
#pragma unroll 4
    for (int c = 0; c < CH; ++c) {
        unsigned long long v = rf[(unsigned long long)c * P64];   // coalesced LDG.64
        const ulonglong2* wrow = (const ulonglong2*)(&Wd[c][0]);  // 4x LDS.128 broadcast
        ulonglong2 w01 = wrow[0];
        ulonglong2 w23 = wrow[1];
        ulonglong2 w45 = wrow[2];
        ulonglong2 w6p = wrow[3];
        acc[0] = fma2(v, w01.x, acc[0]);
        acc[1] = fma2(v, w01.y, acc[1]);
        acc[2] = fma2(v, w23.x, acc[2]);
        acc[3] = fma2(v, w23.y, acc[3]);
        acc[4] = fma2(v, w45.x, acc[4]);
        acc[5] = fma2(v, w45.y, acc[5]);
        acc[6] = fma2(v, w6p.x, acc[6]);
    }

    // ---- Softmax over 7 nodes, per packed half
    float s0[NODES], s1[NODES];
#pragma unroll
    for (int n = 0; n < NODES; ++n) {
        float a, bb;
        unpack2(acc[n], a, bb);
        s0[n] = a + n2s[n];
        s1[n] = bb + n2s[n];
    }
    float m0 = s0[0], m1 = s1[0];
#pragma unroll
    for (int n = 1; n < NODES; ++n) { m0 = fmaxf(m0, s0[n]); m1 = fmaxf(m1, s1[n]); }
    float e0[NODES], e1[NODES];
    float sum0 = 0.f, sum1 = 0.f;
#pragma unroll
    for (int n = 0; n < NODES; ++n) {
        e0[n] = __expf(s0[n] - m0); sum0 += e0[n];
        e1[n] = __expf(s1[n] - m1); sum1 += e1[n];
    }
    float i0 = __fdividef(1.f, sum0);
    float i1 = __fdividef(1.f, sum1);
    unsigned long long attn2[NODES];
#pragma unroll
    for (int n = 0; n < NODES; ++n) attn2[n] = pack2(e0[n] * i0, e1[n] * i1);

    // ---- Pass 2: out[c, p] = relu(sum_n attn[p, n] * new_weight[n, c])
    unsigned long long* outp =
        (unsigned long long*)out + (unsigned long long)b * CH * P64 + gidx;
#pragma unroll 4
    for (int c = 0; c < CH; ++c) {
        const ulonglong2* nr = (const ulonglong2*)(&NWd[c][0]);
        ulonglong2 a01 = nr[0];
        ulonglong2 a23 = nr[1];
        ulonglong2 a45 = nr[2];
        ulonglong2 a6p = nr[3];
        unsigned long long o = 0ull;
        o = fma2(attn2[0], a01.x, o);
        o = fma2(attn2[1], a01.y, o);
        o = fma2(attn2[2], a23.x, o);
        o = fma2(attn2[3], a23.y, o);
        o = fma2(attn2[4], a45.x, o);
        o = fma2(attn2[5], a45.y, o);
        o = fma2(attn2[6], a6p.x, o);
        float lo, hi;
        unpack2(o, lo, hi);
        lo = fmaxf(lo, 0.f);
        hi = fmaxf(hi, 0.f);
        outp[(unsigned long long)c * P64] = pack2(lo, hi);   // coalesced STG.64
    }
}

// ---------------------------------------------------------------------------
extern "C" void kernel_launch(void* const* d_in, const int* in_sizes, int n_in,
                              void* d_out, int out_size) {
    const float* inp    = (const float*)d_in[0];  // [1,2,7,128]
    const float* res    = (const float*)d_in[1];  // [2,256,16,64,64]
    const float* Wres   = (const float*)d_in[2];  // [256,7]
    const float* nfh    = (const float*)d_in[3];  // [128,1]
    const float* weight = (const float*)d_in[4];  // [128,256]

    precompute_kernel<<<14, 256>>>(inp, nfh, weight);
    main_kernel<<<512, 128>>>(res, Wres, (float*)d_out);
}

// round 2
// speedup vs baseline: 1.2004x; 1.2004x over previous
#include <cuda_runtime.h>

#define NODES 7
#define CH 256
#define HID 128
#define P_TOTAL 65536           // 16*64*64
#define P64 (P_TOTAL / 2)       // u64 (2-point) granularity

__device__ float g_nw[2 * NODES * CH];   // new_weight [b, n, c]
__device__ float g_n2[2 * NODES];        // n2 [b, n]

// ---------------------------------------------------------------------------
// Packed f32x2 helpers
// ---------------------------------------------------------------------------
__device__ __forceinline__ unsigned long long fma2(unsigned long long a,
                                                   unsigned long long b,
                                                   unsigned long long c) {
    unsigned long long d;
    asm("fma.rn.f32x2 %0, %1, %2, %3;" : "=l"(d) : "l"(a), "l"(b), "l"(c));
    return d;
}
__device__ __forceinline__ unsigned long long pack2(float x, float y) {
    unsigned long long r;
    asm("mov.b64 %0, {%1, %2};" : "=l"(r) : "f"(x), "f"(y));
    return r;
}
__device__ __forceinline__ void unpack2(unsigned long long v, float& x, float& y) {
    asm("mov.b64 {%0, %1}, %2;" : "=f"(x), "=f"(y) : "l"(v));
}
__device__ __forceinline__ unsigned long long ldcs64(const unsigned long long* p) {
    unsigned long long v;
    asm volatile("ld.global.cs.b64 %0, [%1];" : "=l"(v) : "l"(p));
    return v;
}
__device__ __forceinline__ void stcs64(unsigned long long* p, unsigned long long v) {
    asm volatile("st.global.cs.b64 [%0], %1;" :: "l"(p), "l"(v));
}

// ---------------------------------------------------------------------------
// Precompute: new_weight = inp @ weight [2,7,256], n2 = inp @ nfh [2,7]
// One block per (b, n); 256 threads (one per output channel).
// ---------------------------------------------------------------------------
__global__ void precompute_kernel(const float* __restrict__ inp,
                                  const float* __restrict__ nfh,
                                  const float* __restrict__ weight) {
    int bn = blockIdx.x;            // 0..13
    int c  = threadIdx.x;           // 0..255
    __shared__ float sh_inp[HID];
    if (c < HID) sh_inp[c] = inp[bn * HID + c];
    __syncthreads();
    float acc = 0.f;
#pragma unroll 16
    for (int h = 0; h < HID; ++h)
        acc += sh_inp[h] * weight[h * CH + c];
    g_nw[bn * CH + c] = acc;
    // n2 via warp 0 shuffle reduction
    if (c < 32) {
        float s = 0.f;
#pragma unroll
        for (int i = 0; i < 4; ++i)
            s += sh_inp[c + 32 * i] * nfh[c + 32 * i];
#pragma unroll
        for (int o = 16; o; o >>= 1)
            s += __shfl_xor_sync(0xffffffffu, s, o);
        if (c == 0) g_n2[bn] = s;
    }
}

// ---------------------------------------------------------------------------
// Fused main kernel. Each thread owns 2 consecutive spatial points (u64 lane).
// Pass 1 is software-pipelined 8 deep to keep ~28KB/SM of loads in flight.
// ---------------------------------------------------------------------------
__global__ void __launch_bounds__(128) main_kernel(
    const float* __restrict__ res,     // [2, 256, 65536]
    const float* __restrict__ Wres,    // [256, 7]
    float* __restrict__ out)           // [2, 256, 65536]
{
    __shared__ unsigned long long Wd[CH][8];   // duplicated node_fea_for_res
    __shared__ unsigned long long NWd[CH][8];  // duplicated new_weight (this batch)

    const int tid  = threadIdx.x;
    const int b    = blockIdx.x >> 8;   // 0..1
    const int tile = blockIdx.x & 255;  // 0..255

    for (int c = tid; c < CH; c += 128) {
#pragma unroll
        for (int n = 0; n < NODES; ++n) {
            float w  = Wres[c * NODES + n];
            Wd[c][n] = pack2(w, w);
            float nw = g_nw[(b * NODES + n) * CH + c];
            NWd[c][n] = pack2(nw, nw);
        }
        Wd[c][7]  = 0ull;
        NWd[c][7] = 0ull;
    }
    float n2s[NODES];
#pragma unroll
    for (int n = 0; n < NODES; ++n) n2s[n] = g_n2[b * NODES + n];
    __syncthreads();

    const unsigned long long gidx = (unsigned long long)tile * 128 + tid;
    const unsigned long long* rf =
        (const unsigned long long*)res + (unsigned long long)b * CH * P64 + gidx;

    unsigned long long acc[NODES];
#pragma unroll
    for (int n = 0; n < NODES; ++n) acc[n] = 0ull;

    // ---- Pass 1: n1[p,n] = sum_c rf[c,p] * Wres[c,n] (8-deep pipelined)
    unsigned long long buf[8];
#pragma unroll
    for (int i = 0; i < 8; ++i)
        buf[i] = ldcs64(rf + (unsigned long long)i * P64);

#pragma unroll 1
    for (int cb = 0; cb < CH; cb += 8) {
        unsigned long long cur[8];
#pragma unroll
        for (int i = 0; i < 8; ++i) cur[i] = buf[i];
        if (cb + 8 < CH) {
#pragma unroll
            for (int i = 0; i < 8; ++i)
                buf[i] = ldcs64(rf + (unsigned long long)(cb + 8 + i) * P64);
        }
#pragma unroll
        for (int i = 0; i < 8; ++i) {
            const int c = cb + i;
            const ulonglong2* wrow = (const ulonglong2*)(&Wd[c][0]);
            ulonglong2 w01 = wrow[0];
            ulonglong2 w23 = wrow[1];
            ulonglong2 w45 = wrow[2];
            ulonglong2 w6p = wrow[3];
            unsigned long long v = cur[i];
            acc[0] = fma2(v, w01.x, acc[0]);
            acc[1] = fma2(v, w01.y, acc[1]);
            acc[2] = fma2(v, w23.x, acc[2]);
            acc[3] = fma2(v, w23.y, acc[3]);
            acc[4] = fma2(v, w45.x, acc[4]);
            acc[5] = fma2(v, w45.y, acc[5]);
            acc[6] = fma2(v, w6p.x, acc[6]);
        }
    }

    // ---- Softmax over 7 nodes, per packed half
    float s0[NODES], s1[NODES];
#pragma unroll
    for (int n = 0; n < NODES; ++n) {
        float a, bb;
        unpack2(acc[n], a, bb);
        s0[n] = a + n2s[n];
        s1[n] = bb + n2s[n];
    }
    float m0 = s0[0], m1 = s1[0];
#pragma unroll
    for (int n = 1; n < NODES; ++n) { m0 = fmaxf(m0, s0[n]); m1 = fmaxf(m1, s1[n]); }
    float e0[NODES], e1[NODES];
    float sum0 = 0.f, sum1 = 0.f;
#pragma unroll
    for (int n = 0; n < NODES; ++n) {
        e0[n] = __expf(s0[n] - m0); sum0 += e0[n];
        e1[n] = __expf(s1[n] - m1); sum1 += e1[n];
    }
    float i0 = __fdividef(1.f, sum0);
    float i1 = __fdividef(1.f, sum1);
    unsigned long long attn2[NODES];
#pragma unroll
    for (int n = 0; n < NODES; ++n) attn2[n] = pack2(e0[n] * i0, e1[n] * i1);

    // ---- Pass 2: out[c,p] = relu(sum_n attn[p,n] * new_weight[n,c])
    unsigned long long* outp =
        (unsigned long long*)out + (unsigned long long)b * CH * P64 + gidx;
#pragma unroll 8
    for (int c = 0; c < CH; ++c) {
        const ulonglong2* nr = (const ulonglong2*)(&NWd[c][0]);
        ulonglong2 a01 = nr[0];
        ulonglong2 a23 = nr[1];
        ulonglong2 a45 = nr[2];
        ulonglong2 a6p = nr[3];
        unsigned long long o = 0ull;
        o = fma2(attn2[0], a01.x, o);
        o = fma2(attn2[1], a01.y, o);
        o = fma2(attn2[2], a23.x, o);
        o = fma2(attn2[3], a23.y, o);
        o = fma2(attn2[4], a45.x, o);
        o = fma2(attn2[5], a45.y, o);
        o = fma2(attn2[6], a6p.x, o);
        float lo, hi;
        unpack2(o, lo, hi);
        lo = fmaxf(lo, 0.f);
        hi = fmaxf(hi, 0.f);
        stcs64(outp + (unsigned long long)c * P64, pack2(lo, hi));
    }
}

// ---------------------------------------------------------------------------
extern "C" void kernel_launch(void* const* d_in, const int* in_sizes, int n_in,
                              void* d_out, int out_size) {
    const float* inp    = (const float*)d_in[0];  // [1,2,7,128]
    const float* res    = (const float*)d_in[1];  // [2,256,16,64,64]
    const float* Wres   = (const float*)d_in[2];  // [256,7]
    const float* nfh    = (const float*)d_in[3];  // [128,1]
    const float* weight = (const float*)d_in[4];  // [128,256]

    precompute_kernel<<<14, 256>>>(inp, nfh, weight);
    main_kernel<<<512, 128>>>(res, Wres, (float*)d_out);
}

// round 3
// speedup vs baseline: 1.4370x; 1.1971x over previous
#include <cuda_runtime.h>

#define NODES 7
#define CH 256
#define PAIRS 128               // CH/2 channel pairs
#define HID 128
#define P_TOTAL 65536           // 16*64*64
#define PF 8                    // prefetch depth in channel pairs

__device__ float g_nw[2 * NODES * CH];   // new_weight [b, n, c]
__device__ float g_n2[2 * NODES];        // n2 [b, n]

// ---------------------------------------------------------------------------
// Packed f32x2 helpers
// ---------------------------------------------------------------------------
__device__ __forceinline__ unsigned long long fma2(unsigned long long a,
                                                   unsigned long long b,
                                                   unsigned long long c) {
    unsigned long long d;
    asm("fma.rn.f32x2 %0, %1, %2, %3;" : "=l"(d) : "l"(a), "l"(b), "l"(c));
    return d;
}
__device__ __forceinline__ unsigned long long pack2(float x, float y) {
    unsigned long long r;
    asm("mov.b64 %0, {%1, %2};" : "=l"(r) : "f"(x), "f"(y));
    return r;
}
__device__ __forceinline__ void unpack2(unsigned long long v, float& x, float& y) {
    asm("mov.b64 {%0, %1}, %2;" : "=f"(x), "=f"(y) : "l"(v));
}
__device__ __forceinline__ float ldcs32(const float* p) {
    float v;
    asm volatile("ld.global.cs.b32 %0, [%1];" : "=f"(v) : "l"(p));
    return v;
}
__device__ __forceinline__ void stcs32(float* p, float v) {
    asm volatile("st.global.cs.b32 [%0], %1;" :: "l"(p), "f"(v));
}

// ---------------------------------------------------------------------------
// Precompute: new_weight = inp @ weight [2,7,256], n2 = inp @ nfh [2,7]
// ---------------------------------------------------------------------------
__global__ void precompute_kernel(const float* __restrict__ inp,
                                  const float* __restrict__ nfh,
                                  const float* __restrict__ weight) {
    int bn = blockIdx.x;            // 0..13
    int c  = threadIdx.x;           // 0..255
    __shared__ float sh_inp[HID];
    if (c < HID) sh_inp[c] = inp[bn * HID + c];
    __syncthreads();
    float acc = 0.f;
#pragma unroll 16
    for (int h = 0; h < HID; ++h)
        acc += sh_inp[h] * weight[h * CH + c];
    g_nw[bn * CH + c] = acc;
    if (c < 32) {
        float s = 0.f;
#pragma unroll
        for (int i = 0; i < 4; ++i)
            s += sh_inp[c + 32 * i] * nfh[c + 32 * i];
#pragma unroll
        for (int o = 16; o; o >>= 1)
            s += __shfl_xor_sync(0xffffffffu, s, o);
        if (c == 0) g_n2[bn] = s;
    }
}

// ---------------------------------------------------------------------------
// Fused main kernel: one spatial point per thread; f32x2 lanes carry a
// channel PAIR (2k, 2k+1). Grid 512 x 256 threads (131072 threads).
// ---------------------------------------------------------------------------
__global__ void __launch_bounds__(256) main_kernel(
    const float* __restrict__ res,     // [2, 256, 65536]
    const float* __restrict__ Wres,    // [256, 7]
    float* __restrict__ out)           // [2, 256, 65536]
{
    __shared__ unsigned long long W2[PAIRS][8];   // (w[2k][n], w[2k+1][n])
    __shared__ unsigned long long NW2[PAIRS][8];  // (nw[n][2k], nw[n][2k+1])

    const int tid  = threadIdx.x;
    const int b    = blockIdx.x >> 8;   // 0..1
    const int tile = blockIdx.x & 255;  // 0..255

    // Stage packed channel-pair weights (threads 0..127 take one pair each)
    if (tid < PAIRS) {
        const int k = tid;
#pragma unroll
        for (int n = 0; n < NODES; ++n) {
            float w0 = Wres[(2 * k) * NODES + n];
            float w1 = Wres[(2 * k + 1) * NODES + n];
            W2[k][n] = pack2(w0, w1);
            float q0 = g_nw[(b * NODES + n) * CH + 2 * k];
            float q1 = g_nw[(b * NODES + n) * CH + 2 * k + 1];
            NW2[k][n] = pack2(q0, q1);
        }
        W2[k][7]  = 0ull;
        NW2[k][7] = 0ull;
    }
    float n2s[NODES];
#pragma unroll
    for (int n = 0; n < NODES; ++n) n2s[n] = g_n2[b * NODES + n];
    __syncthreads();

    const int p = tile * 256 + tid;                      // spatial point
    const float* rfp = res + (size_t)b * CH * P_TOTAL + p;

    unsigned long long acc[NODES];
#pragma unroll
    for (int n = 0; n < NODES; ++n) acc[n] = 0ull;

    // ---- Pass 1: n1[p,n] = sum_c rf[c,p]*W[c,n]; lo/hi = even/odd channels
    float a0[PF], a1[PF];
#pragma unroll
    for (int i = 0; i < PF; ++i) {
        a0[i] = ldcs32(rfp + (size_t)(2 * i) * P_TOTAL);
        a1[i] = ldcs32(rfp + (size_t)(2 * i + 1) * P_TOTAL);
    }

#pragma unroll 1
    for (int kb = 0; kb < PAIRS; kb += PF) {
#pragma unroll
        for (int i = 0; i < PF; ++i) {
            unsigned long long v = pack2(a0[i], a1[i]);
            if (kb + PF < PAIRS) {
                a0[i] = ldcs32(rfp + (size_t)(2 * (kb + PF + i)) * P_TOTAL);
                a1[i] = ldcs32(rfp + (size_t)(2 * (kb + PF + i) + 1) * P_TOTAL);
            }
            const ulonglong2* wr = (const ulonglong2*)(&W2[kb + i][0]);
            ulonglong2 w01 = wr[0];
            ulonglong2 w23 = wr[1];
            ulonglong2 w45 = wr[2];
            ulonglong2 w6p = wr[3];
            acc[0] = fma2(v, w01.x, acc[0]);
            acc[1] = fma2(v, w01.y, acc[1]);
            acc[2] = fma2(v, w23.x, acc[2]);
            acc[3] = fma2(v, w23.y, acc[3]);
            acc[4] = fma2(v, w45.x, acc[4]);
            acc[5] = fma2(v, w45.y, acc[5]);
            acc[6] = fma2(v, w6p.x, acc[6]);
        }
    }

    // ---- Softmax over 7 nodes (scalar, one point)
    float s[NODES];
#pragma unroll
    for (int n = 0; n < NODES; ++n) {
        float lo, hi;
        unpack2(acc[n], lo, hi);
        s[n] = lo + hi + n2s[n];
    }
    float m = s[0];
#pragma unroll
    for (int n = 1; n < NODES; ++n) m = fmaxf(m, s[n]);
    float e[NODES], sum = 0.f;
#pragma unroll
    for (int n = 0; n < NODES; ++n) { e[n] = __expf(s[n] - m); sum += e[n]; }
    float inv = __fdividef(1.f, sum);
    unsigned long long attn2[NODES];
#pragma unroll
    for (int n = 0; n < NODES; ++n) {
        float a = e[n] * inv;
        attn2[n] = pack2(a, a);
    }

    // ---- Pass 2: out[c,p] = relu(sum_n attn[n]*nw[n,c]), 2 channels per fma2
    float* op = out + (size_t)b * CH * P_TOTAL + p;
#pragma unroll 4
    for (int k = 0; k < PAIRS; ++k) {
        const ulonglong2* nr = (const ulonglong2*)(&NW2[k][0]);
        ulonglong2 q01 = nr[0];
        ulonglong2 q23 = nr[1];
        ulonglong2 q45 = nr[2];
        ulonglong2 q6p = nr[3];
        unsigned long long o = 0ull;
        o = fma2(attn2[0], q01.x, o);
        o = fma2(attn2[1], q01.y, o);
        o = fma2(attn2[2], q23.x, o);
        o = fma2(attn2[3], q23.y, o);
        o = fma2(attn2[4], q45.x, o);
        o = fma2(attn2[5], q45.y, o);
        o = fma2(attn2[6], q6p.x, o);
        float v0, v1;
        unpack2(o, v0, v1);
        stcs32(op + (size_t)(2 * k) * P_TOTAL, fmaxf(v0, 0.f));
        stcs32(op + (size_t)(2 * k + 1) * P_TOTAL, fmaxf(v1, 0.f));
    }
}

// ---------------------------------------------------------------------------
extern "C" void kernel_launch(void* const* d_in, const int* in_sizes, int n_in,
                              void* d_out, int out_size) {
    const float* inp    = (const float*)d_in[0];  // [1,2,7,128]
    const float* res    = (const float*)d_in[1];  // [2,256,16,64,64]
    const float* Wres   = (const float*)d_in[2];  // [256,7]
    const float* nfh    = (const float*)d_in[3];  // [128,1]
    const float* weight = (const float*)d_in[4];  // [128,256]

    precompute_kernel<<<14, 256>>>(inp, nfh, weight);
    main_kernel<<<512, 256>>>(res, Wres, (float*)d_out);
}

// round 4
// speedup vs baseline: 1.4821x; 1.0314x over previous
#include <cuda_runtime.h>

#define NODES 7
#define CH 256
#define PAIRS 128               // CH/2 channel pairs
#define HID 128
#define P_TOTAL 65536           // 16*64*64
#define PF 8                    // prefetch depth (channel pairs)

__device__ float g_nw[2 * NODES * CH];   // new_weight [b, n, c]
__device__ float g_n2[2 * NODES];        // n2 [b, n]

// ---------------------------------------------------------------------------
// Packed f32x2 helpers
// ---------------------------------------------------------------------------
__device__ __forceinline__ unsigned long long fma2(unsigned long long a,
                                                   unsigned long long b,
                                                   unsigned long long c) {
    unsigned long long d;
    asm("fma.rn.f32x2 %0, %1, %2, %3;" : "=l"(d) : "l"(a), "l"(b), "l"(c));
    return d;
}
__device__ __forceinline__ unsigned long long pack2(float x, float y) {
    unsigned long long r;
    asm("mov.b64 %0, {%1, %2};" : "=l"(r) : "f"(x), "f"(y));
    return r;
}
__device__ __forceinline__ void unpack2(unsigned long long v, float& x, float& y) {
    asm("mov.b64 {%0, %1}, %2;" : "=f"(x), "=f"(y) : "l"(v));
}
__device__ __forceinline__ float ldcs32(const float* p) {
    float v;
    asm volatile("ld.global.cs.b32 %0, [%1];" : "=f"(v) : "l"(p));
    return v;
}
__device__ __forceinline__ void stcs32(float* p, float v) {
    asm volatile("st.global.cs.b32 [%0], %1;" :: "l"(p), "f"(v));
}

// ---------------------------------------------------------------------------
// Precompute: new_weight = inp @ weight [2,7,256], n2 = inp @ nfh [2,7]
// ---------------------------------------------------------------------------
__global__ void precompute_kernel(const float* __restrict__ inp,
                                  const float* __restrict__ nfh,
                                  const float* __restrict__ weight) {
    int bn = blockIdx.x;            // 0..13
    int c  = threadIdx.x;           // 0..255
    __shared__ float sh_inp[HID];
    if (c < HID) sh_inp[c] = inp[bn * HID + c];
    __syncthreads();
    float acc = 0.f;
#pragma unroll 16
    for (int h = 0; h < HID; ++h)
        acc += sh_inp[h] * weight[h * CH + c];
    g_nw[bn * CH + c] = acc;
    if (c < 32) {
        float s = 0.f;
#pragma unroll
        for (int i = 0; i < 4; ++i)
            s += sh_inp[c + 32 * i] * nfh[c + 32 * i];
#pragma unroll
        for (int o = 16; o; o >>= 1)
            s += __shfl_xor_sync(0xffffffffu, s, o);
        if (c == 0) g_n2[bn] = s;
    }
}

// ---------------------------------------------------------------------------
// Fused main kernel, channel-split x2:
//   threads 0..127  -> channels [0,128)   of points [base, base+128)
//   threads 128..255-> channels [128,256) of the same points
// Each thread: f32x2 lanes carry a channel pair. Halves exchange 7 partial
// sums via shared memory; softmax computed redundantly in both halves.
// Grid: 1024 blocks x 256 threads = 262144 threads.
// ---------------------------------------------------------------------------
__global__ void __launch_bounds__(256, 4) main_kernel(
    const float* __restrict__ res,     // [2, 256, 65536]
    const float* __restrict__ Wres,    // [256, 7]
    float* __restrict__ out)           // [2, 256, 65536]
{
    __shared__ unsigned long long W2[PAIRS][8];   // (w[2k][n], w[2k+1][n])
    __shared__ unsigned long long NW2[PAIRS][8];  // (nw[n][2k], nw[n][2k+1])
    __shared__ float part[NODES][2][128];         // partial n1 sums per half

    const int tid  = threadIdx.x;
    const int half = tid >> 7;          // channel half 0/1
    const int pl   = tid & 127;         // local point id
    const int b    = blockIdx.x >> 9;   // 0..1
    const int p    = (blockIdx.x & 511) * 128 + pl;

    // Stage packed channel-pair weights (threads 0..127, one pair each)
    if (tid < PAIRS) {
        const int k = tid;
#pragma unroll
        for (int n = 0; n < NODES; ++n) {
            float w0 = Wres[(2 * k) * NODES + n];
            float w1 = Wres[(2 * k + 1) * NODES + n];
            W2[k][n] = pack2(w0, w1);
            float q0 = g_nw[(b * NODES + n) * CH + 2 * k];
            float q1 = g_nw[(b * NODES + n) * CH + 2 * k + 1];
            NW2[k][n] = pack2(q0, q1);
        }
        W2[k][7]  = 0ull;
        NW2[k][7] = 0ull;
    }
    float n2s[NODES];
#pragma unroll
    for (int n = 0; n < NODES; ++n) n2s[n] = g_n2[b * NODES + n];
    __syncthreads();

    // Base pointer already offset to this thread's channel half
    const float* rfp = res + (size_t)b * CH * P_TOTAL
                           + (size_t)(half * 128) * P_TOTAL + p;

    unsigned long long acc[NODES];
#pragma unroll
    for (int n = 0; n < NODES; ++n) acc[n] = 0ull;

    // ---- Pass 1: partial n1 over this thread's 64 channel pairs
    float a0[PF], a1[PF];
#pragma unroll
    for (int i = 0; i < PF; ++i) {
        a0[i] = ldcs32(rfp + (size_t)(2 * i) * P_TOTAL);
        a1[i] = ldcs32(rfp + (size_t)(2 * i + 1) * P_TOTAL);
    }

    const int kbase = half * 64;        // global pair index base
#pragma unroll 1
    for (int jb = 0; jb < 64; jb += PF) {
#pragma unroll
        for (int i = 0; i < PF; ++i) {
            unsigned long long v = pack2(a0[i], a1[i]);
            if (jb + PF < 64) {
                a0[i] = ldcs32(rfp + (size_t)(2 * (jb + PF + i)) * P_TOTAL);
                a1[i] = ldcs32(rfp + (size_t)(2 * (jb + PF + i) + 1) * P_TOTAL);
            }
            const ulonglong2* wr = (const ulonglong2*)(&W2[kbase + jb + i][0]);
            ulonglong2 w01 = wr[0];
            ulonglong2 w23 = wr[1];
            ulonglong2 w45 = wr[2];
            ulonglong2 w6p = wr[3];
            acc[0] = fma2(v, w01.x, acc[0]);
            acc[1] = fma2(v, w01.y, acc[1]);
            acc[2] = fma2(v, w23.x, acc[2]);
            acc[3] = fma2(v, w23.y, acc[3]);
            acc[4] = fma2(v, w45.x, acc[4]);
            acc[5] = fma2(v, w45.y, acc[5]);
            acc[6] = fma2(v, w6p.x, acc[6]);
        }
    }

    // ---- Exchange partial sums between halves
    float myp[NODES];
#pragma unroll
    for (int n = 0; n < NODES; ++n) {
        float lo, hi;
        unpack2(acc[n], lo, hi);
        myp[n] = lo + hi;
        part[n][half][pl] = myp[n];
    }
    __syncthreads();

    float s[NODES];
#pragma unroll
    for (int n = 0; n < NODES; ++n)
        s[n] = myp[n] + part[n][half ^ 1][pl] + n2s[n];

    // ---- Softmax over 7 nodes
    float m = s[0];
#pragma unroll
    for (int n = 1; n < NODES; ++n) m = fmaxf(m, s[n]);
    float e[NODES], sum = 0.f;
#pragma unroll
    for (int n = 0; n < NODES; ++n) { e[n] = __expf(s[n] - m); sum += e[n]; }
    float inv = __fdividef(1.f, sum);
    unsigned long long attn2[NODES];
#pragma unroll
    for (int n = 0; n < NODES; ++n) {
        float a = e[n] * inv;
        attn2[n] = pack2(a, a);
    }

    // ---- Pass 2: this thread's 64 channel pairs of the output
    float* op = out + (size_t)b * CH * P_TOTAL
                    + (size_t)(half * 128) * P_TOTAL + p;
#pragma unroll 4
    for (int j = 0; j < 64; ++j) {
        const ulonglong2* nr = (const ulonglong2*)(&NW2[kbase + j][0]);
        ulonglong2 q01 = nr[0];
        ulonglong2 q23 = nr[1];
        ulonglong2 q45 = nr[2];
        ulonglong2 q6p = nr[3];
        unsigned long long o = 0ull;
        o = fma2(attn2[0], q01.x, o);
        o = fma2(attn2[1], q01.y, o);
        o = fma2(attn2[2], q23.x, o);
        o = fma2(attn2[3], q23.y, o);
        o = fma2(attn2[4], q45.x, o);
        o = fma2(attn2[5], q45.y, o);
        o = fma2(attn2[6], q6p.x, o);
        float v0, v1;
        unpack2(o, v0, v1);
        stcs32(op + (size_t)(2 * j) * P_TOTAL, fmaxf(v0, 0.f));
        stcs32(op + (size_t)(2 * j + 1) * P_TOTAL, fmaxf(v1, 0.f));
    }
}

// ---------------------------------------------------------------------------
extern "C" void kernel_launch(void* const* d_in, const int* in_sizes, int n_in,
                              void* d_out, int out_size) {
    const float* inp    = (const float*)d_in[0];  // [1,2,7,128]
    const float* res    = (const float*)d_in[1];  // [2,256,16,64,64]
    const float* Wres   = (const float*)d_in[2];  // [256,7]
    const float* nfh    = (const float*)d_in[3];  // [128,1]
    const float* weight = (const float*)d_in[4];  // [128,256]

    precompute_kernel<<<14, 256>>>(inp, nfh, weight);
    main_kernel<<<1024, 256>>>(res, Wres, (float*)d_out);
}